// round 13
// baseline (speedup 1.0000x reference)
#include <cuda_runtime.h>

// QHadamard: y = FWHT_4096(x) / 64, rows = 8192, DIM = 4096.
// R4/R11 body (traffic-minimal: 192 L1 wavefronts/warp) + register-prefetch
// row loop: each block processes 4 consecutive rows; the next row's 32 LDGs
// issue immediately after the current row's T1 smem writes (x[] is dead
// there), hiding the ~600-cycle DRAM latency behind pass B + pass C.
//   A: bits {5..9}  (scalar LDG/STS)   B: bits {0..4} (f4 smem, in-place)
//   C: bits {10,11} (f4 smem read; dense f4 STG)
// Swizzle phys(e) = e ^ ((e & 0xE0) >> 3) -- conflict-free in all phases.
// lb(128,6): 85-reg budget for the 64-float peak live set (x in flight + y).

#define DIM 4096
#define THREADS 128
#define RPB 4                                   // rows per block

__device__ __forceinline__ void bfly(float& a, float& b) {
    float t = a; a = t + b; b = t - b;
}

__device__ __forceinline__ void fwht32(float* x) {
#pragma unroll
    for (int h = 1; h < 32; h <<= 1)
#pragma unroll
        for (int i = 0; i < 32; i += (h << 1))
#pragma unroll
            for (int j = i; j < i + h; ++j) bfly(x[j], x[j + h]);
}

__global__ void __launch_bounds__(THREADS, 6)
QHadamard_24524263260380_kernel(const float* __restrict__ in,
                                float* __restrict__ out) {
    __shared__ float s[DIM];                    // 16 KB, swizzled layout

    const int    T    = threadIdx.x;            // 0..127
    const size_t row0 = (size_t)blockIdx.x * RPB;

    const int   abase  = (T & 31) + ((T >> 5) << 10);     // e{0..4}, e{10,11}
    const int   base4  = T * 8;                            // pass B f4 base
    const int   bxor   = T & 7;
    const int   cbase4 = (T & 31) + (((T >> 5) & 3) << 5); // pass C f4 base
    const int   cxor4  = (T >> 3) & 7;
    const float scale  = 0.015625f;                        // 1/sqrt(4096)

    // ---- Prologue: load row0 ----
    float x[32];
    {
        const float* g = in + row0 * DIM;
#pragma unroll
        for (int k = 0; k < 32; ++k) x[k] = g[abase + (k << 5)];
    }

    for (int i = 0; i < RPB; ++i) {
        // ---- Pass A: FWHT over bits {5..9}, scale folded in ----
#pragma unroll
        for (int k = 0; k < 32; ++k) x[k] *= scale;
        fwht32(x);

        // smem must be free of the previous iteration's pass-C reads
        // (cross-warp) before T1 rewrites it.
        __syncthreads();

        // ---- T1 write: s[swz(e)], swz = e ^ ((k&7)<<2) ----
#pragma unroll
        for (int k = 0; k < 32; ++k) {
            s[(abase + (k << 5)) ^ ((k & 7) << 2)] = x[k];
        }

        // ---- Register prefetch: x is dead now; start next row's loads.
        //      Latency overlaps pass B + pass C + stores. ----
        if (i + 1 < RPB) {
            const float* gn = in + (row0 + i + 1) * DIM;
#pragma unroll
            for (int k = 0; k < 32; ++k) x[k] = gn[abase + (k << 5)];
        }

        // A->B exchange is intra-warp (pass-B thread reads only its own
        // warp's T1 region): warp-local sync suffices.
        __syncwarp(0xffffffffu);

        // ---- Pass B: 32 contiguous elements/thread, f4 smem in-place ----
        {
            float y[32];
            float4* s4 = reinterpret_cast<float4*>(s);
#pragma unroll
            for (int r = 0; r < 8; ++r) {
                float4 v = s4[base4 + (r ^ bxor)];
                y[r*4+0] = v.x; y[r*4+1] = v.y; y[r*4+2] = v.z; y[r*4+3] = v.w;
            }
            fwht32(y);                          // FWHT over bits 0..4
#pragma unroll
            for (int r = 0; r < 8; ++r) {
                s4[base4 + (r ^ bxor)] =
                    make_float4(y[r*4+0], y[r*4+1], y[r*4+2], y[r*4+3]);
            }
        }
        __syncthreads();                        // B->C spans all warps

        // ---- Pass C: f4 reads, FWHT over bits {10,11}, dense f4 stores ----
        {
            float z[32];
            const float4* s4 = reinterpret_cast<const float4*>(s);
#pragma unroll
            for (int rr = 0; rr < 4; ++rr)
#pragma unroll
                for (int s9 = 0; s9 < 2; ++s9) {
                    float4 v = s4[(cbase4 + (s9 << 7) + (rr << 8)) ^ cxor4];
                    const int ix = (rr << 3) + (s9 << 2);
                    z[ix] = v.x; z[ix+1] = v.y; z[ix+2] = v.z; z[ix+3] = v.w;
                }
            // FWHT over bits {10,11} = z-index bits {3,4}
#pragma unroll
            for (int hi = 0; hi < 32; hi += 16)
#pragma unroll
                for (int j = 0; j < 8; ++j) bfly(z[hi + j], z[hi + j + 8]);
#pragma unroll
            for (int j = 0; j < 16; ++j) bfly(z[j], z[j + 16]);

            float4* o4 = reinterpret_cast<float4*>(out + (row0 + i) * DIM);
#pragma unroll
            for (int rr = 0; rr < 4; ++rr)
#pragma unroll
                for (int s9 = 0; s9 < 2; ++s9) {
                    const int ix = (rr << 3) + (s9 << 2);
                    o4[cbase4 + (s9 << 7) + (rr << 8)] =
                        make_float4(z[ix], z[ix+1], z[ix+2], z[ix+3]);
                }
        }
    }
}

extern "C" void kernel_launch(void* const* d_in, const int* in_sizes, int n_in,
                              void* d_out, int out_size) {
    const float* x   = (const float*)d_in[0];
    float*       out = (float*)d_out;
    const int rows = in_sizes[0] / DIM;          // 8192
    QHadamard_24524263260380_kernel<<<rows / RPB, THREADS>>>(x, out);
}

// round 14
// speedup vs baseline: 1.2718x; 1.2718x over previous
#include <cuda_runtime.h>

// QHadamard: y = FWHT_4096(x) / 64, rows = 8192, DIM = 4096.
// FINAL (converged optimum over 13 rounds): R4/R11 structure.
// 3 scalar register passes, 2 smem transposes, 0 shuffles, lb(128,8),
// regs=56 (natural, no spills), 16KB smem/block.
//   A: bits {5..9}  (thread owns e{0..4} lanes + e{10,11} warp; scalar LDG/STS)
//   B: bits {0..4}  (32 contiguous elem/thread; float4 smem in-place)
//   C: bits {10,11} (float4 smem read; dense float4 STG)
// Swizzle phys(e) = e ^ ((e & 0xE0) >> 3) -- conflict-free in all phases.
// A->B exchange is intra-warp -> __syncwarp; B->C spans warps -> __syncthreads.
// Mapped dead ends: more occupancy (spills), packed f32x2 (issue not binding),
// cache hints (zero reuse), cp.async/register prefetch (extra traffic/spills),
// shuffle butterflies (crossbar cost), 16/64-elem granularities (instr. count).

#define DIM 4096
#define THREADS 128

__device__ __forceinline__ void bfly(float& a, float& b) {
    float t = a; a = t + b; b = t - b;
}

__device__ __forceinline__ void fwht32(float* x) {
#pragma unroll
    for (int h = 1; h < 32; h <<= 1)
#pragma unroll
        for (int i = 0; i < 32; i += (h << 1))
#pragma unroll
            for (int j = i; j < i + h; ++j) bfly(x[j], x[j + h]);
}

__global__ void __launch_bounds__(THREADS, 8)
QHadamard_24524263260380_kernel(const float* __restrict__ in,
                                float* __restrict__ out) {
    __shared__ float s[DIM];                      // 16 KB, swizzled layout

    const int    T   = threadIdx.x;               // 0..127
    const size_t row = (size_t)blockIdx.x * DIM;
    const float* g   = in + row;

    // ---- Pass A: e = (T&31) + k*32 + (T>>5)*1024, k = 0..31 -> bits {5..9} ----
    const int abase = (T & 31) + ((T >> 5) << 10);
    float x[32];
#pragma unroll
    for (int k = 0; k < 32; ++k) x[k] = g[abase + (k << 5)];

    const float scale = 0.015625f;                // 1/sqrt(4096)
#pragma unroll
    for (int k = 0; k < 32; ++k) x[k] *= scale;

    fwht32(x);                                    // FWHT over bits 5..9

    // ---- T1 write: s[swz(e)], swz = e ^ ((k&7)<<2). Banks = lane ^ const. ----
#pragma unroll
    for (int k = 0; k < 32; ++k) {
        s[(abase + (k << 5)) ^ ((k & 7) << 2)] = x[k];
    }
    // A->B exchange is intra-warp: warp-local sync suffices.
    __syncwarp(0xffffffffu);

    // ---- Pass B: thread T = e>>5 owns 32 contiguous elements. f4 in/out. ----
    float y[32];
    {
        const int base4 = T * 8;                  // float4 index of e = T*32
        float4* s4 = reinterpret_cast<float4*>(s);
#pragma unroll
        for (int r = 0; r < 8; ++r) {
            float4 v = s4[base4 + (r ^ (T & 7))];
            y[r*4+0] = v.x; y[r*4+1] = v.y; y[r*4+2] = v.z; y[r*4+3] = v.w;
        }
        fwht32(y);                                // FWHT over bits 0..4
#pragma unroll
        for (int r = 0; r < 8; ++r) {
            s4[base4 + (r ^ (T & 7))] =
                make_float4(y[r*4+0], y[r*4+1], y[r*4+2], y[r*4+3]);
        }
    }
    __syncthreads();                              // B->C spans all warps

    // ---- Pass C: base bits{2..6}=T&31, {7,8}=(T>>5)&3; owns {0,1,9,10,11} ----
    const int cbase4 = (T & 31) + (((T >> 5) & 3) << 5);   // float4 index
    const int cxor4  = (T >> 3) & 7;                       // swizzle in f4 units
    float z[32];
    {
        const float4* s4 = reinterpret_cast<const float4*>(s);
#pragma unroll
        for (int rr = 0; rr < 4; ++rr)
#pragma unroll
            for (int s9 = 0; s9 < 2; ++s9) {
                float4 v = s4[(cbase4 + (s9 << 7) + (rr << 8)) ^ cxor4];
                const int i = (rr << 3) + (s9 << 2);
                z[i] = v.x; z[i+1] = v.y; z[i+2] = v.z; z[i+3] = v.w;
            }
    }
    // FWHT over bits {10,11} = z-index bits {3,4}
#pragma unroll
    for (int hi = 0; hi < 32; hi += 16)
#pragma unroll
        for (int j = 0; j < 8; ++j) bfly(z[hi + j], z[hi + j + 8]);
#pragma unroll
    for (int j = 0; j < 16; ++j) bfly(z[j], z[j + 16]);

    // ---- Dense float4 stores: per instr lanes write 32 contiguous float4 ----
    float4* o4 = reinterpret_cast<float4*>(out + row);
#pragma unroll
    for (int rr = 0; rr < 4; ++rr)
#pragma unroll
        for (int s9 = 0; s9 < 2; ++s9) {
            const int i = (rr << 3) + (s9 << 2);
            o4[cbase4 + (s9 << 7) + (rr << 8)] =
                make_float4(z[i], z[i+1], z[i+2], z[i+3]);
        }
}

extern "C" void kernel_launch(void* const* d_in, const int* in_sizes, int n_in,
                              void* d_out, int out_size) {
    const float* x   = (const float*)d_in[0];
    float*       out = (float*)d_out;
    const int rows = in_sizes[0] / DIM;            // 8192
    QHadamard_24524263260380_kernel<<<rows, THREADS>>>(x, out);
}